// round 1
// baseline (speedup 1.0000x reference)
#include <cuda_runtime.h>
#include <cuda_bf16.h>
#include <cstdint>

#define N_ROWS   4194304
#define N_DIM    64
#define N_IMG    1024

// scratch accumulators (no allocation allowed)
__device__ float g_sums[N_IMG * N_DIM];
__device__ int   g_counts[N_IMG];

// ---------------------------------------------------------------------------
// Kernel 1: zero the scratch (runs every graph replay)
// ---------------------------------------------------------------------------
__global__ void zero_kernel() {
    int tid = blockIdx.x * blockDim.x + threadIdx.x;
    if (tid < N_IMG * N_DIM) g_sums[tid] = 0.0f;
    if (tid < N_IMG)         g_counts[tid] = 0;
}

// ---------------------------------------------------------------------------
// Kernel 2: segment sums + counts + id copy.
// grid = 4096 blocks x 256 threads (8 warps). Each warp owns 128 contiguous
// rows. Lane l accumulates dims [2l, 2l+1] as float2 in registers; a flush
// (atomicAdd) happens only at segment boundaries or range end. With ~4096
// rows per segment, flushes are ~1 per warp -> atomics are negligible.
// Also: grid-stride vectorized copy of image_id -> out (as float).
// ---------------------------------------------------------------------------
#define BLOCKS   4096
#define THREADS  256
#define WARPS_PER_BLOCK (THREADS / 32)
#define ROWS_PER_WARP (N_ROWS / (BLOCKS * WARPS_PER_BLOCK))   // = 128

__global__ __launch_bounds__(THREADS, 4)
void main_kernel(const float* __restrict__ x,
                 const int* __restrict__ image_id,
                 float* __restrict__ out) {
    // ---- fused id copy: 4,194,304 ints / 4 per thread = exactly 1M threads
    {
        int tid = blockIdx.x * blockDim.x + threadIdx.x;   // 0 .. 1048575
        const int4* src = reinterpret_cast<const int4*>(image_id);
        float4* dst = reinterpret_cast<float4*>(out + N_IMG * N_DIM);
        int4 v = src[tid];
        dst[tid] = make_float4((float)v.x, (float)v.y, (float)v.z, (float)v.w);
    }

    // ---- warp-owned contiguous row range
    int gwarp = blockIdx.x * WARPS_PER_BLOCK + (threadIdx.x >> 5);
    int lane  = threadIdx.x & 31;
    int row0  = gwarp * ROWS_PER_WARP;

    const float2* __restrict__ x2 = reinterpret_cast<const float2*>(x);

    float2 acc = make_float2(0.0f, 0.0f);
    int cur = __ldg(&image_id[row0]);
    int runlen = 0;

    #pragma unroll 4
    for (int r = row0; r < row0 + ROWS_PER_WARP; ++r) {
        int id = __ldg(&image_id[r]);            // same address all lanes -> L1 broadcast
        if (id != cur) {
            // flush accumulated segment
            atomicAdd(&g_sums[cur * N_DIM + lane * 2 + 0], acc.x);
            atomicAdd(&g_sums[cur * N_DIM + lane * 2 + 1], acc.y);
            if (lane == 0) atomicAdd(&g_counts[cur], runlen);
            acc = make_float2(0.0f, 0.0f);
            cur = id;
            runlen = 0;
        }
        float2 v = x2[(size_t)r * (N_DIM / 2) + lane];   // 256B coalesced per warp
        acc.x += v.x;
        acc.y += v.y;
        ++runlen;
    }
    // final flush
    atomicAdd(&g_sums[cur * N_DIM + lane * 2 + 0], acc.x);
    atomicAdd(&g_sums[cur * N_DIM + lane * 2 + 1], acc.y);
    if (lane == 0) atomicAdd(&g_counts[cur], runlen);
}

// ---------------------------------------------------------------------------
// Kernel 3: finalize -> averaged [1024*64] at out[0], counts at the tail.
// ---------------------------------------------------------------------------
__global__ void finalize_kernel(float* __restrict__ out) {
    int tid = blockIdx.x * blockDim.x + threadIdx.x;
    if (tid < N_IMG * N_DIM) {
        int img = tid >> 6;  // /64
        int c = g_counts[img];
        float denom = (float)(c > 0 ? c : 1);
        out[tid] = g_sums[tid] / denom;
    }
    if (tid < N_IMG) {
        out[N_IMG * N_DIM + N_ROWS + tid] = (float)g_counts[tid];
    }
}

// ---------------------------------------------------------------------------
extern "C" void kernel_launch(void* const* d_in, const int* in_sizes, int n_in,
                              void* d_out, int out_size) {
    // identify inputs by size for robustness:
    //   x: N_ROWS*N_DIM,  image_id: N_ROWS,  n_images: 1 (scalar, ignored)
    const float* x = nullptr;
    const int* image_id = nullptr;
    for (int i = 0; i < n_in; ++i) {
        if (in_sizes[i] == N_ROWS * N_DIM) x = (const float*)d_in[i];
        else if (in_sizes[i] == N_ROWS)    image_id = (const int*)d_in[i];
    }
    float* out = (float*)d_out;

    zero_kernel<<<(N_IMG * N_DIM + 255) / 256, 256>>>();
    main_kernel<<<BLOCKS, THREADS>>>(x, image_id, out);
    finalize_kernel<<<(N_IMG * N_DIM + 255) / 256, 256>>>(out);
}

// round 2
// speedup vs baseline: 1.0776x; 1.0776x over previous
#include <cuda_runtime.h>
#include <cuda_bf16.h>
#include <cstdint>

#define N_ROWS   4194304
#define N_DIM    64
#define N_IMG    1024

// scratch accumulators (no allocation allowed)
__device__ float g_sums[N_IMG * N_DIM];
__device__ int   g_counts[N_IMG];

// ---------------------------------------------------------------------------
// Kernel 1: zero the scratch (runs every graph replay)
// ---------------------------------------------------------------------------
__global__ void zero_kernel() {
    int tid = blockIdx.x * blockDim.x + threadIdx.x;
    if (tid < N_IMG * N_DIM) g_sums[tid] = 0.0f;
    if (tid < N_IMG)         g_counts[tid] = 0;
}

// ---------------------------------------------------------------------------
// Kernel 2: segment sums + counts + id copy.
// grid = 4096 blocks x 256 threads (8 warps). Each warp owns 128 contiguous
// rows. ids are SORTED: a 128-row range has an interior boundary only if
// id[row0] != id[row0+127]  (~3% of warps). Fast path is a branch-free,
// fully unrolled float4 streaming loop: 2 rows / warp-iteration,
// lanes 0-15 -> even row, lanes 16-31 -> odd row, each lane 4 dims.
// ---------------------------------------------------------------------------
#define BLOCKS   4096
#define THREADS  256
#define WARPS_PER_BLOCK (THREADS / 32)
#define ROWS_PER_WARP (N_ROWS / (BLOCKS * WARPS_PER_BLOCK))   // = 128

__global__ __launch_bounds__(THREADS, 4)
void main_kernel(const float* __restrict__ x,
                 const int* __restrict__ image_id,
                 float* __restrict__ out) {
    // ---- fused id copy: 4,194,304 ints / 4 per thread = exactly 1M threads
    {
        int tid = blockIdx.x * blockDim.x + threadIdx.x;   // 0 .. 1048575
        const int4* src = reinterpret_cast<const int4*>(image_id);
        float4* dst = reinterpret_cast<float4*>(out + N_IMG * N_DIM);
        int4 v = __ldcs(&src[tid]);
        dst[tid] = make_float4((float)v.x, (float)v.y, (float)v.z, (float)v.w);
    }

    int gwarp = blockIdx.x * WARPS_PER_BLOCK + (threadIdx.x >> 5);
    int lane  = threadIdx.x & 31;
    int row0  = gwarp * ROWS_PER_WARP;

    int id_first = __ldg(&image_id[row0]);
    int id_last  = __ldg(&image_id[row0 + ROWS_PER_WARP - 1]);

    if (id_first == id_last) {
        // ---------------- FAST PATH (~97% of warps): single segment ----------
        int half = lane >> 4;        // 0: even rows, 1: odd rows
        int sub  = lane & 15;        // float4 slot within the row (4 dims)
        const float4* __restrict__ p =
            reinterpret_cast<const float4*>(x) +
            (size_t)(row0 + half) * (N_DIM / 4) + sub;

        float4 acc = make_float4(0.f, 0.f, 0.f, 0.f);
        #pragma unroll 8
        for (int i = 0; i < ROWS_PER_WARP / 2; ++i) {
            float4 v = __ldcs(p + (size_t)i * (2 * N_DIM / 4));  // stride = 2 rows
            acc.x += v.x; acc.y += v.y; acc.z += v.z; acc.w += v.w;
        }
        // combine the two halves (lane l and l+16 hold the same 4 dims)
        acc.x += __shfl_down_sync(0xffffffff, acc.x, 16);
        acc.y += __shfl_down_sync(0xffffffff, acc.y, 16);
        acc.z += __shfl_down_sync(0xffffffff, acc.z, 16);
        acc.w += __shfl_down_sync(0xffffffff, acc.w, 16);
        if (half == 0) {
            float* s = &g_sums[id_first * N_DIM + sub * 4];
            atomicAdd(s + 0, acc.x);
            atomicAdd(s + 1, acc.y);
            atomicAdd(s + 2, acc.z);
            atomicAdd(s + 3, acc.w);
        }
        if (lane == 0) atomicAdd(&g_counts[id_first], ROWS_PER_WARP);
    } else {
        // ---------------- SLOW PATH (~3%): boundary inside the range ---------
        const float2* __restrict__ x2 = reinterpret_cast<const float2*>(x);
        float2 acc = make_float2(0.0f, 0.0f);
        int cur = id_first;
        int runlen = 0;

        for (int r = row0; r < row0 + ROWS_PER_WARP; ++r) {
            int id = __ldg(&image_id[r]);
            if (id != cur) {
                atomicAdd(&g_sums[cur * N_DIM + lane * 2 + 0], acc.x);
                atomicAdd(&g_sums[cur * N_DIM + lane * 2 + 1], acc.y);
                if (lane == 0) atomicAdd(&g_counts[cur], runlen);
                acc = make_float2(0.0f, 0.0f);
                cur = id;
                runlen = 0;
            }
            float2 v = __ldcs(&x2[(size_t)r * (N_DIM / 2) + lane]);
            acc.x += v.x;
            acc.y += v.y;
            ++runlen;
        }
        atomicAdd(&g_sums[cur * N_DIM + lane * 2 + 0], acc.x);
        atomicAdd(&g_sums[cur * N_DIM + lane * 2 + 1], acc.y);
        if (lane == 0) atomicAdd(&g_counts[cur], runlen);
    }
}

// ---------------------------------------------------------------------------
// Kernel 3: finalize -> averaged [1024*64] at out[0], counts at the tail.
// ---------------------------------------------------------------------------
__global__ void finalize_kernel(float* __restrict__ out) {
    int tid = blockIdx.x * blockDim.x + threadIdx.x;
    if (tid < N_IMG * N_DIM) {
        int img = tid >> 6;  // /64
        int c = g_counts[img];
        float denom = (float)(c > 0 ? c : 1);
        out[tid] = g_sums[tid] / denom;
    }
    if (tid < N_IMG) {
        out[N_IMG * N_DIM + N_ROWS + tid] = (float)g_counts[tid];
    }
}

// ---------------------------------------------------------------------------
extern "C" void kernel_launch(void* const* d_in, const int* in_sizes, int n_in,
                              void* d_out, int out_size) {
    const float* x = nullptr;
    const int* image_id = nullptr;
    for (int i = 0; i < n_in; ++i) {
        if (in_sizes[i] == N_ROWS * N_DIM) x = (const float*)d_in[i];
        else if (in_sizes[i] == N_ROWS)    image_id = (const int*)d_in[i];
    }
    float* out = (float*)d_out;

    zero_kernel<<<(N_IMG * N_DIM + 255) / 256, 256>>>();
    main_kernel<<<BLOCKS, THREADS>>>(x, image_id, out);
    finalize_kernel<<<(N_IMG * N_DIM + 255) / 256, 256>>>(out);
}